// round 4
// baseline (speedup 1.0000x reference)
#include <cuda_runtime.h>
#include <cstddef>

#define HH 512
#define WW 512
#define CC 64
#define HWSZ (HH*WW)
#define KS 576
#define WQ_SIZE 36864
#define MAGF 12582912.0f   // 1.5 * 2^23 -> round-half-even via magic add

// ---------------- scratch (no allocations allowed) ----------------
__device__ float g_part[9 * 64 * 64];   // [kk][c][hb] per-block partial act maxes
__device__ float g_qm2[9 * 64];         // [k][c] : 1/(scale_j * s_x)
__device__ float g_sx;                  // s_x

// ---------------- packed f32x2 helpers ----------------
__device__ __forceinline__ unsigned long long fma2_(unsigned long long a,
                                                    unsigned long long b,
                                                    unsigned long long c) {
    unsigned long long d;
    asm("fma.rn.f32x2 %0, %1, %2, %3;" : "=l"(d) : "l"(a), "l"(b), "l"(c));
    return d;
}
__device__ __forceinline__ unsigned long long add2_(unsigned long long a,
                                                    unsigned long long b) {
    unsigned long long d;
    asm("add.rn.f32x2 %0, %1, %2;" : "=l"(d) : "l"(a), "l"(b));
    return d;
}
__device__ __forceinline__ unsigned long long mul2_(unsigned long long a,
                                                    unsigned long long b) {
    unsigned long long d;
    asm("mul.rn.f32x2 %0, %1, %2;" : "=l"(d) : "l"(a), "l"(b));
    return d;
}
__device__ __forceinline__ unsigned long long pack2(float x) {
    unsigned u = __float_as_uint(x);
    return ((unsigned long long)u << 32) | u;
}

// 9 taps: returns Sum_k round(v*m_k).
// EXACTNESS: each t_k = MAG + r_k with |r_k| <= 127 lives in [2^23, 2^24) where
// ulp = 1. Running acc = t_0 + Sum (t_k - MAG) stays within MAG +- 1143, i.e.
// NEVER leaves [2^23, 2^24), so every add is exact integer arithmetic.
// (The R2 bug: summing the biased terms first pushed partials past 2^24.)
__device__ __forceinline__ unsigned long long taps9(unsigned long long v2,
                                                    const unsigned long long* m,
                                                    unsigned long long MAG2,
                                                    unsigned long long NMAG2) {
    unsigned long long acc = fma2_(v2, m[0], MAG2);
#pragma unroll
    for (int k = 1; k < 9; k++) {
        unsigned long long t = fma2_(v2, m[k], MAG2);
        acc = add2_(acc, add2_(t, NMAG2));
    }
    return add2_(acc, NMAG2);          // acc - MAG = Sum round(v*m_k), exact
}

// ---------------- K1: per-(c,kh,kw) activation abs-max partials ----------------
__global__ __launch_bounds__(256) void k1_actmax(const float* __restrict__ in) {
    int c    = blockIdx.x;          // 64
    int hb   = blockIdx.y;          // 64 groups of 8 rows
    int warp = threadIdx.x >> 5;
    int lane = threadIdx.x & 31;

    const float* row = in + (size_t)c * HWSZ + (size_t)(hb * 8 + warp) * WW + lane * 16;
    float v[16];
#pragma unroll
    for (int i = 0; i < 4; i++) {
        float4 t = *(const float4*)(row + i * 4);
        v[i*4+0] = fabsf(t.x); v[i*4+1] = fabsf(t.y);
        v[i*4+2] = fabsf(t.z); v[i*4+3] = fabsf(t.w);
    }
    float mMid = v[1];
#pragma unroll
    for (int i = 2; i < 15; i++) mMid = fmaxf(mMid, v[i]);

    // core = max over this row's interior cols (0<w<511); borders tracked separately
    float core;
    if (lane == 0)       core = fmaxf(mMid, v[15]);
    else if (lane == 31) core = fmaxf(mMid, v[0]);
    else                 core = fmaxf(fmaxf(mMid, v[0]), v[15]);

    __shared__ float s_core[8], s_v0[8], s_v511[8];
    if (lane == 0)  s_v0[warp]   = v[0];      // col 0 (abs)
    if (lane == 31) s_v511[warp] = v[15];     // col 511 (abs)
    unsigned r = __reduce_max_sync(0xffffffffu, (unsigned)__float_as_int(core));
    if (lane == 0) s_core[warp] = __int_as_float((int)r);
    __syncthreads();

    if (threadIdx.x < 9) {
        int kh = threadIdx.x / 3, kw = threadIdx.x % 3;
        int r0 = (kh == 2 && hb == 0)  ? 1 : 0;   // kh=2 excludes global row 0
        int r1 = (kh == 0 && hb == 63) ? 7 : 8;   // kh=0 excludes global row 511
        float mx = 0.f;
        for (int rr = r0; rr < r1; rr++) {
            float t = s_core[rr];
            if (kw != 2) t = fmaxf(t, s_v0[rr]);     // kw 0,1 include col 0
            if (kw != 0) t = fmaxf(t, s_v511[rr]);   // kw 1,2 include col 511
            mx = fmaxf(mx, t);
        }
        g_part[threadIdx.x * 4096 + c * 64 + hb] = mx;
    }
}

// ---------------- K2: reduce partials, scales, s_x, s_w, quantized weight ----------------
__global__ __launch_bounds__(576) void k2_scales(const float* __restrict__ wgt,
                                                 float* __restrict__ out_wq) {
    int j = threadIdx.x;            // j = c*9 + kk
    int c = j / 9, kk = j % 9;
    __shared__ float sA[18], sW[18];
    __shared__ float sh_ax, sh_aw;

    float act = 0.f;
    const float* pp = g_part + kk * 4096 + c * 64;
#pragma unroll 8
    for (int r = 0; r < 64; r++) act = fmaxf(act, pp[r]);

    float wmax = 0.f;
#pragma unroll 8
    for (int co = 0; co < 64; co++)
        wmax = fmaxf(wmax, fabsf(wgt[co * KS + j]));

    float scale = sqrtf(act) / sqrtf(wmax);   // alpha = 0.5
    if (scale == 0.f) scale = 1.f;
    float candx = act / scale;                // column max of |x/scale|
    float candw = wmax * scale;               // column max of |w*scale|

    unsigned rx = __reduce_max_sync(0xffffffffu, (unsigned)__float_as_int(candx));
    unsigned rw = __reduce_max_sync(0xffffffffu, (unsigned)__float_as_int(candw));
    if ((j & 31) == 0) { sA[j >> 5] = __int_as_float((int)rx);
                         sW[j >> 5] = __int_as_float((int)rw); }
    __syncthreads();
    if (j == 0) {
        float ax = 0.f, aw = 0.f;
        for (int r = 0; r < 18; r++) { ax = fmaxf(ax, sA[r]); aw = fmaxf(aw, sW[r]); }
        sh_ax = ax; sh_aw = aw;
    }
    __syncthreads();

    float sx = (sh_ax > 0.f) ? (sh_ax / 127.0f) : 1.f;
    float sw = (sh_aw > 0.f) ? (sh_aw / 127.0f) : 1.f;

    g_qm2[kk * 64 + c] = 1.0f / (scale * sx);   // [k][c] layout for k3
    if (j == 0) g_sx = sx;

    int kh = kk / 3, kw = kk % 3;
    float inv_sw = 1.0f / sw;
#pragma unroll 4
    for (int co = 0; co < 64; co++) {
        float wv = wgt[co * KS + j] * scale;
        float q  = rintf(fminf(fmaxf(wv * inv_sw, -127.f), 127.f));
        out_wq[((co * 3 + kh) * 3 + kw) * 64 + c] = q * sw;
    }
}

// ---------------- K3: fused quantize + fold + NCHW->NHWC (f32x2 packed) ----------------
// xf[h,w,c] = s_x * Sum_{valid (kh,kw)} round( input[c,h,w] * qm[c,kh,kw] )
__global__ __launch_bounds__(256) void k3_fold(const float* __restrict__ in,
                                               float* __restrict__ out) {
    __shared__ float s_in[32][66];     // [pixel][channel], stride 66 keeps 8B align
    __shared__ float s_qm[576];        // flat copy of g_qm2 ([k][c])

    const int h   = blockIdx.y;        // 512
    const int wt  = blockIdx.x;        // 16 tiles of 32 pixels
    const int tid = threadIdx.x;

    for (int i = tid; i < 576; i += 256) s_qm[i] = g_qm2[i];

    const float* base = in + (size_t)h * WW + wt * 32;
    for (int i = tid; i < 512; i += 256) {           // coalesced float4 reads
        int cc = i >> 3, w4 = i & 7;
        float4 t = *(const float4*)(base + (size_t)cc * HWSZ + w4 * 4);
        s_in[w4*4+0][cc] = t.x;
        s_in[w4*4+1][cc] = t.y;
        s_in[w4*4+2][cc] = t.z;
        s_in[w4*4+3][cc] = t.w;
    }
    __syncthreads();

    const int cp = tid & 31;           // channel pair -> channels 2cp, 2cp+1
    const int g  = tid >> 5;           // warp id = pixel group of 4
    const unsigned long long MAG2  = pack2(MAGF);
    const unsigned long long NMAG2 = pack2(-MAGF);
    const unsigned long long sx2   = pack2(g_sx);

    unsigned long long m2[9];
#pragma unroll
    for (int k = 0; k < 9; k++)
        m2[k] = *(const unsigned long long*)&s_qm[k * 64 + 2 * cp];
    if (h == 0)      { m2[6] = 0; m2[7] = 0; m2[8] = 0; }   // kh=2 invalid
    if (h == HH - 1) { m2[0] = 0; m2[1] = 0; m2[2] = 0; }   // kh=0 invalid

    const int w0 = wt * 32 + g * 4;
    float* obase = out + ((size_t)h * WW + w0) * 64 + 2 * cp;
    const bool w_lo = (wt == 0 && g == 0);       // contains w=0   (warp-uniform)
    const bool w_hi = (wt == 15 && g == 7);      // contains w=511 (warp-uniform)

    if (!w_lo && !w_hi) {
#pragma unroll
        for (int p = 0; p < 4; p++) {
            unsigned long long v2 = *(const unsigned long long*)&s_in[g*4+p][2*cp];
            unsigned long long d  = taps9(v2, m2, MAG2, NMAG2);
            *(unsigned long long*)(obase + (size_t)p * 64) = mul2_(d, sx2);
        }
    } else {
#pragma unroll
        for (int p = 0; p < 4; p++) {
            unsigned long long mm[9];
#pragma unroll
            for (int k = 0; k < 9; k++) mm[k] = m2[k];
            if (w_lo && p == 0) { mm[2] = 0; mm[5] = 0; mm[8] = 0; }  // kw=2 invalid @ w=0
            if (w_hi && p == 3) { mm[0] = 0; mm[3] = 0; mm[6] = 0; }  // kw=0 invalid @ w=511
            unsigned long long v2 = *(const unsigned long long*)&s_in[g*4+p][2*cp];
            unsigned long long d  = taps9(v2, mm, MAG2, NMAG2);
            *(unsigned long long*)(obase + (size_t)p * 64) = mul2_(d, sx2);
        }
    }
}

// ---------------- launch ----------------
extern "C" void kernel_launch(void* const* d_in, const int* in_sizes, int n_in,
                              void* d_out, int out_size) {
    const float* inp = (const float*)d_in[0];
    const float* wgt = (const float*)d_in[1];
    if (n_in >= 2 && in_sizes[0] == WQ_SIZE) {   // defensive: swap if order differs
        const float* t = inp; inp = wgt; wgt = t;
    }
    float* out_wq = (float*)d_out;
    float* out_xf = (float*)d_out + WQ_SIZE;

    {
        dim3 grid(64, 64);
        k1_actmax<<<grid, 256>>>(inp);
    }
    k2_scales<<<1, 576>>>(wgt, out_wq);
    {
        dim3 grid(16, 512);
        k3_fold<<<grid, 256>>>(inp, out_xf);
    }
}

// round 5
// speedup vs baseline: 1.0769x; 1.0769x over previous
#include <cuda_runtime.h>
#include <cstddef>

#define HH 512
#define WW 512
#define CC 64
#define HWSZ (HH*WW)
#define KS 576
#define WQ_SIZE 36864
#define MAGF 12582912.0f           // 1.5 * 2^23 -> round-half-even via magic add
#define MAGBITS 0x4B400000u        // bit pattern of MAGF

// ---------------- scratch (no allocations allowed) ----------------
__device__ float g_part[9 * 64 * 32];   // [kk][c][hb] per-block partial act maxes
__device__ float g_qm2[9 * 64];         // [k][c] : 1/(scale_j * s_x)
__device__ float g_sx;                  // s_x

// ---------------- K1: per-(c,kh,kw) activation abs-max partials ----------------
// Each block: one channel, 16 rows. Each warp: 2 rows, 8 LDG.128 front-batched.
__global__ __launch_bounds__(256) void k1_actmax(const float* __restrict__ in) {
    int c    = blockIdx.x;          // 64
    int hb   = blockIdx.y;          // 32 groups of 16 rows
    int warp = threadIdx.x >> 5;    // 8 warps -> rows 2*warp, 2*warp+1
    int lane = threadIdx.x & 31;

    const float* base = in + (size_t)c * HWSZ
                           + (size_t)(hb * 16 + warp * 2) * WW + lane * 16;
    float v[32];
#pragma unroll
    for (int r = 0; r < 2; r++)
#pragma unroll
        for (int i = 0; i < 4; i++) {
            float4 t = *(const float4*)(base + r * WW + i * 4);
            v[r*16 + i*4 + 0] = fabsf(t.x); v[r*16 + i*4 + 1] = fabsf(t.y);
            v[r*16 + i*4 + 2] = fabsf(t.z); v[r*16 + i*4 + 3] = fabsf(t.w);
        }

    __shared__ float s_core[16], s_v0[16], s_v511[16];

#pragma unroll
    for (int r = 0; r < 2; r++) {
        float mMid = v[r*16 + 1];
#pragma unroll
        for (int i = 2; i < 15; i++) mMid = fmaxf(mMid, v[r*16 + i]);
        // core = max over this row's interior cols (0<w<511)
        float core;
        if (lane == 0)       core = fmaxf(mMid, v[r*16 + 15]);
        else if (lane == 31) core = fmaxf(mMid, v[r*16 + 0]);
        else                 core = fmaxf(fmaxf(mMid, v[r*16 + 0]), v[r*16 + 15]);

        unsigned red = __reduce_max_sync(0xffffffffu, (unsigned)__float_as_int(core));
        if (lane == 0) {
            s_core[warp*2 + r] = __int_as_float((int)red);
            s_v0[warp*2 + r]   = v[r*16 + 0];       // col 0 (abs)
        }
        if (lane == 31) s_v511[warp*2 + r] = v[r*16 + 15];  // col 511 (abs)
    }
    __syncthreads();

    if (threadIdx.x < 9) {
        int kh = threadIdx.x / 3, kw = threadIdx.x % 3;
        int r0 = (kh == 2 && hb == 0)  ? 1  : 0;    // kh=2 excludes global row 0
        int r1 = (kh == 0 && hb == 31) ? 15 : 16;   // kh=0 excludes global row 511
        float mx = 0.f;
        for (int rr = r0; rr < r1; rr++) {
            float t = s_core[rr];
            if (kw != 2) t = fmaxf(t, s_v0[rr]);    // kw 0,1 include col 0
            if (kw != 0) t = fmaxf(t, s_v511[rr]);  // kw 1,2 include col 511
            mx = fmaxf(mx, t);
        }
        g_part[threadIdx.x * 2048 + c * 32 + hb] = mx;
    }
}

// ---------------- K2: reduce partials, scales, s_x, s_w, quantized weight ----------------
__global__ __launch_bounds__(576) void k2_scales(const float* __restrict__ wgt,
                                                 float* __restrict__ out_wq) {
    int j = threadIdx.x;            // j = c*9 + kk
    int c = j / 9, kk = j % 9;
    __shared__ float sA[18], sW[18];
    __shared__ float sh_ax, sh_aw;

    float act = 0.f;
    const float* pp = g_part + kk * 2048 + c * 32;
#pragma unroll 8
    for (int r = 0; r < 32; r++) act = fmaxf(act, pp[r]);

    float wmax = 0.f;
#pragma unroll 8
    for (int co = 0; co < 64; co++)
        wmax = fmaxf(wmax, fabsf(wgt[co * KS + j]));

    float scale = sqrtf(act) / sqrtf(wmax);   // alpha = 0.5
    if (scale == 0.f) scale = 1.f;
    float candx = act / scale;                // column max of |x/scale|
    float candw = wmax * scale;               // column max of |w*scale|

    unsigned rx = __reduce_max_sync(0xffffffffu, (unsigned)__float_as_int(candx));
    unsigned rw = __reduce_max_sync(0xffffffffu, (unsigned)__float_as_int(candw));
    if ((j & 31) == 0) { sA[j >> 5] = __int_as_float((int)rx);
                         sW[j >> 5] = __int_as_float((int)rw); }
    __syncthreads();
    if (j == 0) {
        float ax = 0.f, aw = 0.f;
        for (int r = 0; r < 18; r++) { ax = fmaxf(ax, sA[r]); aw = fmaxf(aw, sW[r]); }
        sh_ax = ax; sh_aw = aw;
    }
    __syncthreads();

    float sx = (sh_ax > 0.f) ? (sh_ax / 127.0f) : 1.f;
    float sw = (sh_aw > 0.f) ? (sh_aw / 127.0f) : 1.f;

    g_qm2[kk * 64 + c] = 1.0f / (scale * sx);   // [k][c] layout for k3
    if (j == 0) g_sx = sx;

    int kh = kk / 3, kw = kk % 3;
    float inv_sw = 1.0f / sw;
#pragma unroll 4
    for (int co = 0; co < 64; co++) {
        float wv = wgt[co * KS + j] * scale;
        float q  = rintf(fminf(fmaxf(wv * inv_sw, -127.f), 127.f));
        out_wq[((co * 3 + kh) * 3 + kw) * 64 + c] = q * sw;
    }
}

// ---------------- tap sum via integer-bits accumulation ----------------
// t_k = RN(v*m_k + MAG) lies in [2^23, 2^24)  =>  bits(t_k) = MAGBITS + round(v*m_k)
// with |round(v*m_k)| <= 127.  Sum the 9 bit patterns in wrapping u32 arithmetic,
// subtract 8*MAGBITS (mod 2^32): result bits = MAGBITS + Sum r_k, reinterpret,
// subtract MAG (exact, same binade).  FMA pipe: 9 FFMA + 1 FADD.  ALU pipe: ~5 adds.
__device__ __forceinline__ float taps9i(float v, const float* m) {
    unsigned s = 0u;
#pragma unroll
    for (int k = 0; k < 9; k++)
        s += __float_as_uint(fmaf(v, m[k], MAGF));
    s -= 8u * MAGBITS;                 // wrapping; true value fits in 32 bits
    return __uint_as_float(s) - MAGF;  // = (float)Sum_k round(v*m_k), exact
}

// ---------------- K3: fused quantize + fold + NCHW->NHWC ----------------
// xf[h,w,c] = s_x * Sum_{valid (kh,kw)} round( input[c,h,w] * qm[c,kh,kw] )
__global__ __launch_bounds__(256) void k3_fold(const float* __restrict__ in,
                                               float* __restrict__ out) {
    __shared__ float s_in[32][66];     // [pixel][channel], +2 pad keeps 8B align
    __shared__ float s_qm[576];        // flat copy of g_qm2 ([k][c])

    const int h   = blockIdx.y;        // 512
    const int wt  = blockIdx.x;        // 16 tiles of 32 pixels
    const int tid = threadIdx.x;

    for (int i = tid; i < 576; i += 256) s_qm[i] = g_qm2[i];

    const float* base = in + (size_t)h * WW + wt * 32;
    for (int i = tid; i < 512; i += 256) {           // coalesced float4 reads
        int cc = i >> 3, w4 = i & 7;
        float4 t = *(const float4*)(base + (size_t)cc * HWSZ + w4 * 4);
        s_in[w4*4+0][cc] = t.x;
        s_in[w4*4+1][cc] = t.y;
        s_in[w4*4+2][cc] = t.z;
        s_in[w4*4+3][cc] = t.w;
    }
    __syncthreads();

    const int cp = tid & 31;           // channel pair -> channels 2cp, 2cp+1
    const int g  = tid >> 5;           // warp id = pixel group of 4
    const float sx = g_sx;

    float mA[9], mB[9];
#pragma unroll
    for (int k = 0; k < 9; k++) {
        mA[k] = s_qm[k * 64 + 2 * cp];
        mB[k] = s_qm[k * 64 + 2 * cp + 1];
    }
    if (h == 0)      { mA[6]=mA[7]=mA[8]=0.f; mB[6]=mB[7]=mB[8]=0.f; }  // kh=2 invalid
    if (h == HH - 1) { mA[0]=mA[1]=mA[2]=0.f; mB[0]=mB[1]=mB[2]=0.f; }  // kh=0 invalid

    const int w0 = wt * 32 + g * 4;
    float* obase = out + ((size_t)h * WW + w0) * 64 + 2 * cp;
    const bool w_lo = (wt == 0 && g == 0);       // contains w=0   (warp-uniform)
    const bool w_hi = (wt == 15 && g == 7);      // contains w=511 (warp-uniform)

    if (!w_lo && !w_hi) {
#pragma unroll
        for (int p = 0; p < 4; p++) {
            float2 v = *(const float2*)&s_in[g*4 + p][2*cp];
            float2 r;
            r.x = taps9i(v.x, mA) * sx;
            r.y = taps9i(v.y, mB) * sx;
            *(float2*)(obase + (size_t)p * 64) = r;
        }
    } else {
#pragma unroll
        for (int p = 0; p < 4; p++) {
            float ma[9], mb[9];
#pragma unroll
            for (int k = 0; k < 9; k++) { ma[k] = mA[k]; mb[k] = mB[k]; }
            if (w_lo && p == 0) { ma[2]=ma[5]=ma[8]=0.f; mb[2]=mb[5]=mb[8]=0.f; } // kw=2 @ w=0
            if (w_hi && p == 3) { ma[0]=ma[3]=ma[6]=0.f; mb[0]=mb[3]=mb[6]=0.f; } // kw=0 @ w=511
            float2 v = *(const float2*)&s_in[g*4 + p][2*cp];
            float2 r;
            r.x = taps9i(v.x, ma) * sx;
            r.y = taps9i(v.y, mb) * sx;
            *(float2*)(obase + (size_t)p * 64) = r;
        }
    }
}

// ---------------- launch ----------------
extern "C" void kernel_launch(void* const* d_in, const int* in_sizes, int n_in,
                              void* d_out, int out_size) {
    const float* inp = (const float*)d_in[0];
    const float* wgt = (const float*)d_in[1];
    if (n_in >= 2 && in_sizes[0] == WQ_SIZE) {   // defensive: swap if order differs
        const float* t = inp; inp = wgt; wgt = t;
    }
    float* out_wq = (float*)d_out;
    float* out_xf = (float*)d_out + WQ_SIZE;

    {
        dim3 grid(64, 32);
        k1_actmax<<<grid, 256>>>(inp);
    }
    k2_scales<<<1, 576>>>(wgt, out_wq);
    {
        dim3 grid(16, 512);
        k3_fold<<<grid, 256>>>(inp, out_xf);
    }
}